// round 2
// baseline (speedup 1.0000x reference)
#include <cuda_runtime.h>
#include <math.h>

#define B_  2
#define C_  384
#define HH  32
#define WW  32
#define HW  1024
#define NHEAD 12
#define NGROUP 6
#define HC  32
#define GC  64
#define NS  1024          // n_sample
#define SCALE 0.17677669529663687f   // 1/sqrt(32)

// ---------------- scratch (device globals; no cudaMalloc allowed) -----------
__device__ float g_q  [B_ * C_ * HW];       // q = Wq x + bq            [B,384,1024]
__device__ float g_pos[B_ * NGROUP * NS * 2]; // sampling pos (y,x)     [12,1024,2]
__device__ float g_xs [B_ * NGROUP * GC * NS]; // sampled x             [12,64,1024] == [B,384,1024]
__device__ float g_k  [B_ * C_ * NS];
__device__ float g_v  [B_ * C_ * NS];
__device__ float g_o  [B_ * C_ * HW];       // attention output before Wo

// ---------------- generic 384-in conv1x1 GEMM: Y[b,o,p] = sum_c W[o,c] X[b,c,p] + bias[o]
__global__ void gemm384_kernel(float* __restrict__ Y, const float* __restrict__ W,
                               const float* __restrict__ X, const float* __restrict__ bias) {
    __shared__ float Ws[16][64 + 4];   // [k][o]
    __shared__ float Xs[16][64 + 4];   // [k][p]
    const int P = 1024;
    int b  = blockIdx.z;
    const float* Xb = X + (size_t)b * C_ * P;
    float*       Yb = Y + (size_t)b * C_ * P;
    int o0 = blockIdx.y * 64;
    int p0 = blockIdx.x * 64;
    int tid = threadIdx.x;
    int tx = tid & 15, ty = tid >> 4;           // 16x16 threads
    float acc[4][4] = {};
    for (int k0 = 0; k0 < C_; k0 += 16) {
        #pragma unroll
        for (int i = tid; i < 64 * 16; i += 256) {
            int oo = i >> 4, kk = i & 15;
            Ws[kk][oo] = W[(o0 + oo) * C_ + k0 + kk];
        }
        #pragma unroll
        for (int i = tid; i < 16 * 64; i += 256) {
            int kk = i >> 6, pp = i & 63;
            Xs[kk][pp] = Xb[(size_t)(k0 + kk) * P + p0 + pp];
        }
        __syncthreads();
        #pragma unroll
        for (int kk = 0; kk < 16; kk++) {
            float wv[4], xv[4];
            #pragma unroll
            for (int i = 0; i < 4; i++) wv[i] = Ws[kk][ty * 4 + i];
            #pragma unroll
            for (int j = 0; j < 4; j++) xv[j] = Xs[kk][tx * 4 + j];
            #pragma unroll
            for (int i = 0; i < 4; i++)
                #pragma unroll
                for (int j = 0; j < 4; j++) acc[i][j] += wv[i] * xv[j];
        }
        __syncthreads();
    }
    #pragma unroll
    for (int i = 0; i < 4; i++) {
        int o = o0 + ty * 4 + i;
        float bb = bias ? bias[o] : 0.f;
        #pragma unroll
        for (int j = 0; j < 4; j++)
            Yb[(size_t)o * P + p0 + tx * 4 + j] = acc[i][j] + bb;
    }
}

// ---------------- offset branch: depthwise7x7 + LN(ch) + GELU + pw(2) + tanh -> pos
__global__ void offset_kernel(const float* __restrict__ q,
                              const float* __restrict__ dw_w, const float* __restrict__ dw_b,
                              const float* __restrict__ ln_g, const float* __restrict__ ln_b,
                              const float* __restrict__ pw_w, float* __restrict__ pos) {
    int bs = blockIdx.x;            // bg*1024 + s
    int bg = bs >> 10;
    int s  = bs & 1023;
    int y = s >> 5, x = s & 31;
    int c = threadIdx.x;            // 0..63
    int b = bg / NGROUP, g = bg % NGROUP;
    const float* qc = q + ((size_t)b * C_ + g * GC + c) * HW;
    const float* w  = dw_w + c * 49;
    float acc = dw_b[c];
    #pragma unroll
    for (int dy = 0; dy < 7; dy++) {
        int yy = y + dy - 3;
        if (yy < 0 || yy > 31) continue;
        #pragma unroll
        for (int dx = 0; dx < 7; dx++) {
            int xx = x + dx - 3;
            if (xx < 0 || xx > 31) continue;
            acc += w[dy * 7 + dx] * qc[yy * 32 + xx];
        }
    }
    __shared__ float red_a[2], red_b[2], red_c[2], red_d[2];
    // mean
    float v = acc;
    #pragma unroll
    for (int o = 16; o; o >>= 1) v += __shfl_down_sync(0xffffffffu, v, o);
    if ((c & 31) == 0) red_a[c >> 5] = v;
    __syncthreads();
    float mu = (red_a[0] + red_a[1]) * (1.f / 64.f);
    float d = acc - mu;
    float v2 = d * d;
    #pragma unroll
    for (int o = 16; o; o >>= 1) v2 += __shfl_down_sync(0xffffffffu, v2, o);
    if ((c & 31) == 0) red_b[c >> 5] = v2;
    __syncthreads();
    float var = (red_b[0] + red_b[1]) * (1.f / 64.f);
    float on = d * rsqrtf(var + 1e-5f) * ln_g[c] + ln_b[c];
    float ge = 0.5f * on * (1.f + erff(on * 0.70710678118654752f));
    float p0 = ge * pw_w[c];
    float p1 = ge * pw_w[GC + c];
    #pragma unroll
    for (int o = 16; o; o >>= 1) {
        p0 += __shfl_down_sync(0xffffffffu, p0, o);
        p1 += __shfl_down_sync(0xffffffffu, p1, o);
    }
    if ((c & 31) == 0) { red_c[c >> 5] = p0; red_d[c >> 5] = p1; }
    __syncthreads();
    if (c == 0) {
        float off_y = tanhf(red_c[0] + red_c[1]) * (2.0f / 32.0f);
        float off_x = tanhf(red_d[0] + red_d[1]) * (2.0f / 32.0f);
        float ry = ((float)y + 0.5f) * (1.f / 16.f) - 1.f;
        float rx = ((float)x + 0.5f) * (1.f / 16.f) - 1.f;
        pos[(bg * NS + s) * 2 + 0] = off_y + ry;
        pos[(bg * NS + s) * 2 + 1] = off_x + rx;
    }
}

// ---------------- grid sample of x at pos -> xs[bg][c][s]
__global__ void sample_kernel(const float* __restrict__ x, const float* __restrict__ pos,
                              float* __restrict__ xs) {
    int idx = blockIdx.x * blockDim.x + threadIdx.x;
    if (idx >= B_ * NGROUP * GC * NS) return;
    int s  = idx & 1023;
    int c  = (idx >> 10) & 63;
    int bg = idx >> 16;
    int b = bg / NGROUP, g = bg % NGROUP;
    float py = pos[(bg * NS + s) * 2 + 0];
    float px = pos[(bg * NS + s) * 2 + 1];
    float gx = (px + 1.f) * 0.5f * 31.f;
    float gy = (py + 1.f) * 0.5f * 31.f;
    float x0f = floorf(gx), y0f = floorf(gy);
    float wx = gx - x0f, wy = gy - y0f;
    int x0 = (int)x0f, y0 = (int)y0f;
    const float* img = x + ((size_t)b * C_ + g * GC + c) * HW;
    float acc = 0.f;
    if (x0 >= 0     && x0 <= 31     && y0 >= 0     && y0 <= 31)     acc += (1.f - wx) * (1.f - wy) * img[y0 * 32 + x0];
    if (x0 + 1 >= 0 && x0 + 1 <= 31 && y0 >= 0     && y0 <= 31)     acc += wx * (1.f - wy)         * img[y0 * 32 + x0 + 1];
    if (x0 >= 0     && x0 <= 31     && y0 + 1 >= 0 && y0 + 1 <= 31) acc += (1.f - wx) * wy         * img[(y0 + 1) * 32 + x0];
    if (x0 + 1 >= 0 && x0 + 1 <= 31 && y0 + 1 >= 0 && y0 + 1 <= 31) acc += wx * wy                 * img[(y0 + 1) * 32 + x0 + 1];
    xs[idx] = acc;
}

// ---------------- fused attention: logits (+RPE bias), softmax, P@V
// grid: x = query tile of 8 (128 tiles), y = bh (24). 256 threads.
__global__ void attn_kernel(const float* __restrict__ q, const float* __restrict__ k,
                            const float* __restrict__ v, const float* __restrict__ pos,
                            const float* __restrict__ rpe, float* __restrict__ out) {
    __shared__ float S[8][NS];
    __shared__ float qs[HC][8];
    int bh = blockIdx.y;
    int b = bh / NHEAD, h = bh % NHEAD;
    int g = h >> 1;
    int bg = b * NGROUP + g;
    int m0 = blockIdx.x * 8;
    int tid = threadIdx.x;

    for (int i = tid; i < HC * 8; i += 256) {
        int c = i >> 3, m = i & 7;
        qs[c][m] = q[((size_t)b * C_ + h * HC + c) * HW + m0 + m];
    }
    __syncthreads();

    float qy[8], qx[8];
    #pragma unroll
    for (int m = 0; m < 8; m++) {
        int mg = m0 + m;
        qy[m] = ((float)(mg >> 5) + 0.5f) * (1.f / 16.f) - 1.f;
        qx[m] = ((float)(mg & 31) + 0.5f) * (1.f / 16.f) - 1.f;
    }
    const float* tab = rpe + h * 63 * 63;
    const float* kb  = k + ((size_t)b * C_ + h * HC) * NS;

    for (int n = tid; n < NS; n += 256) {
        float dot[8] = {};
        #pragma unroll
        for (int c = 0; c < HC; c++) {
            float kv = kb[(size_t)c * NS + n];
            #pragma unroll
            for (int m = 0; m < 8; m++) dot[m] += kv * qs[c][m];
        }
        float py = pos[(bg * NS + n) * 2 + 0];
        float px = pos[(bg * NS + n) * 2 + 1];
        #pragma unroll
        for (int m = 0; m < 8; m++) {
            float dyv = (qy[m] - py) * 0.5f;
            float dxv = (qx[m] - px) * 0.5f;
            float gx = (dxv + 1.f) * 31.f;      // 0.5*(63-1)
            float gy = (dyv + 1.f) * 31.f;
            float x0f = floorf(gx), y0f = floorf(gy);
            float wx = gx - x0f, wy = gy - y0f;
            int x0 = (int)x0f, y0 = (int)y0f;
            float bias = 0.f;
            if (x0 >= 0     && x0 <= 62     && y0 >= 0     && y0 <= 62)     bias += (1.f - wx) * (1.f - wy) * tab[y0 * 63 + x0];
            if (x0 + 1 >= 0 && x0 + 1 <= 62 && y0 >= 0     && y0 <= 62)     bias += wx * (1.f - wy)         * tab[y0 * 63 + x0 + 1];
            if (x0 >= 0     && x0 <= 62     && y0 + 1 >= 0 && y0 + 1 <= 62) bias += (1.f - wx) * wy         * tab[(y0 + 1) * 63 + x0];
            if (x0 + 1 >= 0 && x0 + 1 <= 62 && y0 + 1 >= 0 && y0 + 1 <= 62) bias += wx * wy                 * tab[(y0 + 1) * 63 + x0 + 1];
            S[m][n] = dot[m] * SCALE + bias;
        }
    }
    __syncthreads();

    // softmax: warp w owns row w
    int w = tid >> 5, lane = tid & 31;
    {
        float mx = -1e30f;
        for (int n = lane; n < NS; n += 32) mx = fmaxf(mx, S[w][n]);
        #pragma unroll
        for (int o = 16; o; o >>= 1) mx = fmaxf(mx, __shfl_xor_sync(0xffffffffu, mx, o));
        float sum = 0.f;
        for (int n = lane; n < NS; n += 32) {
            float e = __expf(S[w][n] - mx);
            S[w][n] = e;
            sum += e;
        }
        #pragma unroll
        for (int o = 16; o; o >>= 1) sum += __shfl_xor_sync(0xffffffffu, sum, o);
        float inv = 1.f / sum;
        for (int n = lane; n < NS; n += 32) S[w][n] *= inv;
    }
    __syncthreads();

    // out[c][m] = sum_n P[m][n] v[c][n]; thread: c = tid&31, m = tid>>5
    int c = tid & 31, m = tid >> 5;
    const float4* vr = (const float4*)(v + ((size_t)b * C_ + h * HC + c) * NS);
    const float4* pr = (const float4*)(&S[m][0]);
    float acc = 0.f;
    #pragma unroll 4
    for (int n = 0; n < NS / 4; n++) {
        float4 vv = vr[n];
        float4 pp = pr[n];
        acc += pp.x * vv.x + pp.y * vv.y + pp.z * vv.z + pp.w * vv.w;
    }
    out[((size_t)b * C_ + h * HC + c) * HW + m0 + m] = acc;
}

// ---------------- launch -----------------------------------------------------
extern "C" void kernel_launch(void* const* d_in, const int* in_sizes, int n_in,
                              void* d_out, int out_size) {
    const float* x      = (const float*)d_in[0];
    const float* Wq     = (const float*)d_in[1];
    const float* bq     = (const float*)d_in[2];
    const float* Wk     = (const float*)d_in[3];
    const float* bk     = (const float*)d_in[4];
    const float* Wv     = (const float*)d_in[5];
    const float* bv     = (const float*)d_in[6];
    const float* Wo     = (const float*)d_in[7];
    const float* bo     = (const float*)d_in[8];
    const float* dw_w   = (const float*)d_in[9];
    const float* dw_b   = (const float*)d_in[10];
    const float* ln_g   = (const float*)d_in[11];
    const float* ln_b   = (const float*)d_in[12];
    const float* pw_w   = (const float*)d_in[13];
    const float* rpe    = (const float*)d_in[14];
    float* y = (float*)d_out;

    float *q, *pos, *xs, *k, *v, *o;
    cudaGetSymbolAddress((void**)&q,   g_q);
    cudaGetSymbolAddress((void**)&pos, g_pos);
    cudaGetSymbolAddress((void**)&xs,  g_xs);
    cudaGetSymbolAddress((void**)&k,   g_k);
    cudaGetSymbolAddress((void**)&v,   g_v);
    cudaGetSymbolAddress((void**)&o,   g_o);

    dim3 ggrid(16, 6, B_);   // P/64, C/64, B

    // 1) q = Wq x + bq
    gemm384_kernel<<<ggrid, 256>>>(q, Wq, x, bq);
    // 2) offsets -> pos
    offset_kernel<<<B_ * NGROUP * NS, GC>>>(q, dw_w, dw_b, ln_g, ln_b, pw_w, pos);
    // 3) grid sample -> xs
    sample_kernel<<<(B_ * NGROUP * GC * NS + 255) / 256, 256>>>(x, pos, xs);
    // 4) k, v projections
    gemm384_kernel<<<ggrid, 256>>>(k, Wk, xs, bk);
    gemm384_kernel<<<ggrid, 256>>>(v, Wv, xs, bv);
    // 5) fused attention
    dim3 agrid(HW / 8, B_ * NHEAD);
    attn_kernel<<<agrid, 256>>>(q, k, v, pos, rpe, o);
    // 6) y = Wo out + bo
    gemm384_kernel<<<ggrid, 256>>>(y, Wo, o, bo);
}

// round 3
// speedup vs baseline: 2.7692x; 2.7692x over previous
#include <cuda_runtime.h>
#include <math.h>

#define B_  2
#define C_  384
#define HW  1024
#define NHEAD 12
#define NGROUP 6
#define HC  32
#define GC  64
#define NS  1024
#define SCALE 0.17677669529663687f   // 1/sqrt(32)

// ---------------- scratch ----------------------------------------------------
__device__ float g_q  [B_ * C_ * HW];
__device__ float g_pos[B_ * NGROUP * NS * 2];
__device__ float g_xs [B_ * NGROUP * GC * NS];
__device__ float g_k  [B_ * C_ * NS];
__device__ float g_v  [B_ * C_ * NS];
__device__ float g_o  [B_ * C_ * HW];

// ---------------- GEMM: Y[o,p] = sum_c W[o,c] X[c,p] + bias[o] ---------------
// tile 64(o) x 32(p), 128 threads, K-chunk 32
__device__ __forceinline__ void gemm_core(float* __restrict__ Yb, const float* __restrict__ W,
                                          const float* __restrict__ bias,
                                          const float* __restrict__ Xb, int o0, int p0) {
    __shared__ float Wt[64][33];
    __shared__ float Xs[32][32];
    int tid = threadIdx.x;
    int tx = tid & 7, ty = tid >> 3;
    float acc[4][4] = {};
    for (int k0 = 0; k0 < C_; k0 += 32) {
        __syncthreads();
        #pragma unroll
        for (int i = tid; i < 64 * 32; i += 128) {
            int kk = i & 31, oo = i >> 5;
            Wt[oo][kk] = W[(o0 + oo) * C_ + k0 + kk];
        }
        #pragma unroll
        for (int i = tid; i < 32 * 32; i += 128) {
            int pp = i & 31, kk = i >> 5;
            Xs[kk][pp] = Xb[(size_t)(k0 + kk) * HW + p0 + pp];
        }
        __syncthreads();
        #pragma unroll
        for (int kk = 0; kk < 32; kk++) {
            float4 xv = *(const float4*)&Xs[kk][tx * 4];
            float w0 = Wt[ty * 4 + 0][kk];
            float w1 = Wt[ty * 4 + 1][kk];
            float w2 = Wt[ty * 4 + 2][kk];
            float w3 = Wt[ty * 4 + 3][kk];
            acc[0][0] += w0 * xv.x; acc[0][1] += w0 * xv.y; acc[0][2] += w0 * xv.z; acc[0][3] += w0 * xv.w;
            acc[1][0] += w1 * xv.x; acc[1][1] += w1 * xv.y; acc[1][2] += w1 * xv.z; acc[1][3] += w1 * xv.w;
            acc[2][0] += w2 * xv.x; acc[2][1] += w2 * xv.y; acc[2][2] += w2 * xv.z; acc[2][3] += w2 * xv.w;
            acc[3][0] += w3 * xv.x; acc[3][1] += w3 * xv.y; acc[3][2] += w3 * xv.z; acc[3][3] += w3 * xv.w;
        }
    }
    #pragma unroll
    for (int i = 0; i < 4; i++) {
        int o = o0 + ty * 4 + i;
        float bb = bias[o];
        float4 r = make_float4(acc[i][0] + bb, acc[i][1] + bb, acc[i][2] + bb, acc[i][3] + bb);
        *(float4*)&Yb[(size_t)o * HW + p0 + tx * 4] = r;
    }
}

__global__ void gemm2_kernel(float* __restrict__ Y, const float* __restrict__ W,
                             const float* __restrict__ X, const float* __restrict__ bias) {
    int b = blockIdx.z;
    gemm_core(Y + (size_t)b * C_ * HW, W, bias, X + (size_t)b * C_ * HW,
              blockIdx.y * 64, blockIdx.x * 32);
}

// fused K+V projections (grid.y = 12: 0-5 -> K, 6-11 -> V)
__global__ void gemm2_kv_kernel(float* __restrict__ K, const float* __restrict__ Wk, const float* __restrict__ bk,
                                float* __restrict__ V, const float* __restrict__ Wv, const float* __restrict__ bv,
                                const float* __restrict__ X) {
    int b = blockIdx.z;
    int yy = blockIdx.y;
    const float* W = (yy < 6) ? Wk : Wv;
    const float* bb = (yy < 6) ? bk : bv;
    float* Y = (yy < 6) ? K : V;
    gemm_core(Y + (size_t)b * C_ * NS, W, bb, X + (size_t)b * C_ * NS,
              (yy % 6) * 64, blockIdx.x * 32);
}

// ---------------- offset branch ----------------------------------------------
// block: 64 channels x 4 positions
__global__ void offset_kernel(const float* __restrict__ q,
                              const float* __restrict__ dw_w, const float* __restrict__ dw_b,
                              const float* __restrict__ ln_g, const float* __restrict__ ln_b,
                              const float* __restrict__ pw_w, float* __restrict__ pos) {
    int c = threadIdx.x;        // 0..63
    int p = threadIdx.y;        // 0..3
    int bs = blockIdx.x * 4 + p;
    int bg = bs >> 10;
    int s  = bs & 1023;
    int y = s >> 5, x = s & 31;
    int b = bg / NGROUP, g = bg % NGROUP;
    const float* qc = q + ((size_t)b * C_ + g * GC + c) * HW;
    const float* w  = dw_w + c * 49;
    float acc = dw_b[c];
    #pragma unroll
    for (int dy = 0; dy < 7; dy++) {
        int yy = y + dy - 3;
        if (yy < 0 || yy > 31) continue;
        #pragma unroll
        for (int dx = 0; dx < 7; dx++) {
            int xx = x + dx - 3;
            if (xx < 0 || xx > 31) continue;
            acc += w[dy * 7 + dx] * qc[yy * 32 + xx];
        }
    }
    __shared__ float ra[4][2], rb[4][2], rc[4][2], rd[4][2];
    int half = c >> 5;
    float v = acc;
    #pragma unroll
    for (int o = 16; o; o >>= 1) v += __shfl_down_sync(0xffffffffu, v, o);
    if ((c & 31) == 0) ra[p][half] = v;
    __syncthreads();
    float mu = (ra[p][0] + ra[p][1]) * (1.f / 64.f);
    float d = acc - mu;
    float v2 = d * d;
    #pragma unroll
    for (int o = 16; o; o >>= 1) v2 += __shfl_down_sync(0xffffffffu, v2, o);
    if ((c & 31) == 0) rb[p][half] = v2;
    __syncthreads();
    float var = (rb[p][0] + rb[p][1]) * (1.f / 64.f);
    float on = d * rsqrtf(var + 1e-5f) * ln_g[c] + ln_b[c];
    float ge = 0.5f * on * (1.f + erff(on * 0.70710678118654752f));
    float p0 = ge * pw_w[c];
    float p1 = ge * pw_w[GC + c];
    #pragma unroll
    for (int o = 16; o; o >>= 1) {
        p0 += __shfl_down_sync(0xffffffffu, p0, o);
        p1 += __shfl_down_sync(0xffffffffu, p1, o);
    }
    if ((c & 31) == 0) { rc[p][half] = p0; rd[p][half] = p1; }
    __syncthreads();
    if (c == 0) {
        float off_y = tanhf(rc[p][0] + rc[p][1]) * (2.0f / 32.0f);
        float off_x = tanhf(rd[p][0] + rd[p][1]) * (2.0f / 32.0f);
        float ry = ((float)y + 0.5f) * (1.f / 16.f) - 1.f;
        float rx = ((float)x + 0.5f) * (1.f / 16.f) - 1.f;
        pos[(bg * NS + s) * 2 + 0] = off_y + ry;
        pos[(bg * NS + s) * 2 + 1] = off_x + rx;
    }
}

// ---------------- grid sample -> xs ------------------------------------------
__global__ void sample_kernel(const float* __restrict__ x, const float* __restrict__ pos,
                              float* __restrict__ xs) {
    int idx = blockIdx.x * blockDim.x + threadIdx.x;
    if (idx >= B_ * NGROUP * GC * NS) return;
    int s  = idx & 1023;
    int c  = (idx >> 10) & 63;
    int bg = idx >> 16;
    int b = bg / NGROUP, g = bg % NGROUP;
    float py = pos[(bg * NS + s) * 2 + 0];
    float px = pos[(bg * NS + s) * 2 + 1];
    float gx = (px + 1.f) * 0.5f * 31.f;
    float gy = (py + 1.f) * 0.5f * 31.f;
    float x0f = floorf(gx), y0f = floorf(gy);
    float wx = gx - x0f, wy = gy - y0f;
    int x0 = (int)x0f, y0 = (int)y0f;
    const float* img = x + ((size_t)b * C_ + g * GC + c) * HW;
    float acc = 0.f;
    bool x0v = (unsigned)x0 < 32u, x1v = (unsigned)(x0 + 1) < 32u;
    bool y0v = (unsigned)y0 < 32u, y1v = (unsigned)(y0 + 1) < 32u;
    if (x0v && y0v) acc += (1.f - wx) * (1.f - wy) * img[y0 * 32 + x0];
    if (x1v && y0v) acc += wx * (1.f - wy)         * img[y0 * 32 + x0 + 1];
    if (x0v && y1v) acc += (1.f - wx) * wy         * img[(y0 + 1) * 32 + x0];
    if (x1v && y1v) acc += wx * wy                 * img[(y0 + 1) * 32 + x0 + 1];
    xs[idx] = acc;
}

// ---------------- flash-style fused attention --------------------------------
__device__ __forceinline__ float bilin63(const float* __restrict__ tab, float gy, float gx) {
    float x0f = floorf(gx), y0f = floorf(gy);
    float wx = gx - x0f, wy = gy - y0f;
    int x0 = (int)x0f, y0 = (int)y0f;
    bool x0v = (unsigned)x0 < 63u, x1v = (unsigned)(x0 + 1) < 63u;
    bool y0v = (unsigned)y0 < 63u, y1v = (unsigned)(y0 + 1) < 63u;
    float r = 0.f;
    if (x0v && y0v) r += (1.f - wx) * (1.f - wy) * tab[y0 * 63 + x0];
    if (x1v && y0v) r += wx * (1.f - wy)         * tab[y0 * 63 + x0 + 1];
    if (x0v && y1v) r += (1.f - wx) * wy         * tab[(y0 + 1) * 63 + x0];
    if (x1v && y1v) r += wx * wy                 * tab[(y0 + 1) * 63 + x0 + 1];
    return r;
}

// block: 64 queries x (all 1024 samples in 64-tiles), 256 threads = 16x16
__global__ __launch_bounds__(256) void attn2_kernel(
        const float* __restrict__ q, const float* __restrict__ k,
        const float* __restrict__ v, const float* __restrict__ pos,
        const float* __restrict__ rpe, float* __restrict__ out) {
    __shared__ float Qs[32][64];
    __shared__ float Ks[32][64];
    __shared__ float Vs[32][68];
    __shared__ float Ps[64][68];
    __shared__ float posy[64], posx[64];

    int bh = blockIdx.y;
    int b = bh / NHEAD, h = bh % NHEAD;
    int bg = b * NGROUP + (h >> 1);
    int m0 = blockIdx.x * 64;
    int tid = threadIdx.x;
    int tx = tid & 15, ty = tid >> 4;

    const float* qb = q + ((size_t)b * C_ + h * HC) * HW;
    const float* kb = k + ((size_t)b * C_ + h * HC) * NS;
    const float* vb = v + ((size_t)b * C_ + h * HC) * NS;
    const float* tab = rpe + h * 63 * 63;

    #pragma unroll
    for (int i = tid; i < HC * 64; i += 256) {
        int c = i >> 6, m = i & 63;
        Qs[c][m] = qb[(size_t)c * HW + m0 + m];
    }

    float qy[4], qx[4];
    #pragma unroll
    for (int i = 0; i < 4; i++) {
        int mg = m0 + ty * 4 + i;
        qy[i] = ((float)(mg >> 5) + 0.5f) * (1.f / 16.f) - 1.f;
        qx[i] = ((float)(mg & 31) + 0.5f) * (1.f / 16.f) - 1.f;
    }

    float mrow[4] = {-1e30f, -1e30f, -1e30f, -1e30f};
    float lrow[4] = {};
    float O[4][2] = {};

    for (int n0 = 0; n0 < NS; n0 += 64) {
        __syncthreads();
        #pragma unroll
        for (int i = tid; i < HC * 64; i += 256) {
            int c = i >> 6, n = i & 63;
            Ks[c][n] = kb[(size_t)c * NS + n0 + n];
            Vs[c][n] = vb[(size_t)c * NS + n0 + n];
        }
        if (tid < 64) {
            posy[tid] = pos[(bg * NS + n0 + tid) * 2 + 0];
            posx[tid] = pos[(bg * NS + n0 + tid) * 2 + 1];
        }
        __syncthreads();

        // ---- S tile: 4x4 per thread ----
        float s[4][4] = {};
        #pragma unroll
        for (int kk = 0; kk < HC; kk++) {
            float4 xv = *(const float4*)&Ks[kk][tx * 4];
            float4 wv = *(const float4*)&Qs[kk][ty * 4];
            s[0][0] += wv.x * xv.x; s[0][1] += wv.x * xv.y; s[0][2] += wv.x * xv.z; s[0][3] += wv.x * xv.w;
            s[1][0] += wv.y * xv.x; s[1][1] += wv.y * xv.y; s[1][2] += wv.y * xv.z; s[1][3] += wv.y * xv.w;
            s[2][0] += wv.z * xv.x; s[2][1] += wv.z * xv.y; s[2][2] += wv.z * xv.z; s[2][3] += wv.z * xv.w;
            s[3][0] += wv.w * xv.x; s[3][1] += wv.w * xv.y; s[3][2] += wv.w * xv.z; s[3][3] += wv.w * xv.w;
        }
        // ---- RPE bias + scale ----
        #pragma unroll
        for (int j = 0; j < 4; j++) {
            float py = posy[tx * 4 + j];
            float px = posx[tx * 4 + j];
            #pragma unroll
            for (int i = 0; i < 4; i++) {
                float gy = ((qy[i] - py) * 0.5f + 1.f) * 31.f;
                float gx = ((qx[i] - px) * 0.5f + 1.f) * 31.f;
                s[i][j] = s[i][j] * SCALE + bilin63(tab, gy, gx);
            }
        }
        // ---- online softmax ----
        #pragma unroll
        for (int i = 0; i < 4; i++) {
            float tmax = fmaxf(fmaxf(s[i][0], s[i][1]), fmaxf(s[i][2], s[i][3]));
            #pragma unroll
            for (int o = 8; o; o >>= 1) tmax = fmaxf(tmax, __shfl_xor_sync(0xffffffffu, tmax, o));
            float mnew = fmaxf(mrow[i], tmax);
            float alpha = __expf(mrow[i] - mnew);
            mrow[i] = mnew;
            float e0 = __expf(s[i][0] - mnew);
            float e1 = __expf(s[i][1] - mnew);
            float e2 = __expf(s[i][2] - mnew);
            float e3 = __expf(s[i][3] - mnew);
            float4 ev = make_float4(e0, e1, e2, e3);
            *(float4*)&Ps[ty * 4 + i][tx * 4] = ev;
            float rs = e0 + e1 + e2 + e3;
            #pragma unroll
            for (int o = 8; o; o >>= 1) rs += __shfl_xor_sync(0xffffffffu, rs, o);
            lrow[i] = lrow[i] * alpha + rs;
            O[i][0] *= alpha;
            O[i][1] *= alpha;
        }
        __syncthreads();
        // ---- P @ V ----
        #pragma unroll
        for (int nn = 0; nn < 64; nn += 4) {
            float4 v0 = *(const float4*)&Vs[tx][nn];
            float4 v1 = *(const float4*)&Vs[tx + 16][nn];
            #pragma unroll
            for (int i = 0; i < 4; i++) {
                float4 pp = *(const float4*)&Ps[ty * 4 + i][nn];
                O[i][0] += pp.x * v0.x + pp.y * v0.y + pp.z * v0.z + pp.w * v0.w;
                O[i][1] += pp.x * v1.x + pp.y * v1.y + pp.z * v1.z + pp.w * v1.w;
            }
        }
    }

    float* ob = out + ((size_t)b * C_ + h * HC) * HW;
    #pragma unroll
    for (int i = 0; i < 4; i++) {
        float inv = 1.f / lrow[i];
        int m = m0 + ty * 4 + i;
        ob[(size_t)tx * HW + m]        = O[i][0] * inv;
        ob[(size_t)(tx + 16) * HW + m] = O[i][1] * inv;
    }
}

// ---------------- launch -----------------------------------------------------
extern "C" void kernel_launch(void* const* d_in, const int* in_sizes, int n_in,
                              void* d_out, int out_size) {
    const float* x      = (const float*)d_in[0];
    const float* Wq     = (const float*)d_in[1];
    const float* bq     = (const float*)d_in[2];
    const float* Wk     = (const float*)d_in[3];
    const float* bk     = (const float*)d_in[4];
    const float* Wv     = (const float*)d_in[5];
    const float* bv     = (const float*)d_in[6];
    const float* Wo     = (const float*)d_in[7];
    const float* bo     = (const float*)d_in[8];
    const float* dw_w   = (const float*)d_in[9];
    const float* dw_b   = (const float*)d_in[10];
    const float* ln_g   = (const float*)d_in[11];
    const float* ln_b   = (const float*)d_in[12];
    const float* pw_w   = (const float*)d_in[13];
    const float* rpe    = (const float*)d_in[14];
    float* y = (float*)d_out;

    float *q, *pos, *xs, *k, *v, *o;
    cudaGetSymbolAddress((void**)&q,   g_q);
    cudaGetSymbolAddress((void**)&pos, g_pos);
    cudaGetSymbolAddress((void**)&xs,  g_xs);
    cudaGetSymbolAddress((void**)&k,   g_k);
    cudaGetSymbolAddress((void**)&v,   g_v);
    cudaGetSymbolAddress((void**)&o,   g_o);

    dim3 ggrid(32, 6, B_);      // p-tiles, o-tiles, batch

    gemm2_kernel<<<ggrid, 128>>>(q, Wq, x, bq);

    dim3 obk(64, 4);
    offset_kernel<<<B_ * NGROUP * NS / 4, obk>>>(q, dw_w, dw_b, ln_g, ln_b, pw_w, pos);

    sample_kernel<<<(B_ * NGROUP * GC * NS + 255) / 256, 256>>>(x, pos, xs);

    dim3 kvgrid(32, 12, B_);
    gemm2_kv_kernel<<<kvgrid, 128>>>(k, Wk, bk, v, Wv, bv, xs);

    dim3 agrid(HW / 64, B_ * NHEAD);
    attn2_kernel<<<agrid, 256>>>(q, k, v, pos, rpe, o);

    gemm2_kernel<<<ggrid, 128>>>(y, Wo, o, bo);
}